// round 10
// baseline (speedup 1.0000x reference)
#include <cuda_runtime.h>
#include <cuda_bf16.h>

#define BB 4
#define NN 8192
#define CC 1024
#define SS 16
#define NTOK (BB * NN)             // 32768
#define CHUNK 64
#define NCHUNK (NN / CHUNK)        // 128 per batch
#define NCHUNKS_TOT (BB * NCHUNK)  // 512

typedef unsigned long long ull;

// Partial per-token state, TRANSPOSED: [half][state][token], 2 x 2 MB (L2)
__device__ float g_xstate_t[2][SS][NTOK];
// Partial per-chunk raw sums per c-half
__device__ float g_chsum[2][NCHUNKS_TOT * SS];
// Exclusive per-chunk prefixes (combined)
__device__ float g_cprefix[NCHUNKS_TOT * SS];

// ---------- packed f32x2 + async helpers ----------
__device__ __forceinline__ ull dup2(float x) {
    ull r;
    unsigned u = __float_as_uint(x);
    asm("mov.b64 %0, {%1, %1};" : "=l"(r) : "r"(u));
    return r;
}
__device__ __forceinline__ void fma2(ull& d, ull a, ull b) {
    asm("fma.rn.f32x2 %0, %1, %2, %0;" : "+l"(d) : "l"(a), "l"(b));
}
__device__ __forceinline__ ull add2(ull a, ull b) {
    ull r;
    asm("add.rn.f32x2 %0, %1, %2;" : "=l"(r) : "l"(a), "l"(b));
    return r;
}
__device__ __forceinline__ void unpack2(ull v, float& lo, float& hi) {
    unsigned a, b;
    asm("mov.b64 {%0, %1}, %2;" : "=r"(a), "=r"(b) : "l"(v));
    lo = __uint_as_float(a);
    hi = __uint_as_float(b);
}
__device__ __forceinline__ unsigned sptr(const void* p) {
    unsigned r;
    asm("{.reg .u64 t; cvta.to.shared.u64 t, %1; cvt.u32.u64 %0, t;}"
        : "=r"(r) : "l"(p));
    return r;
}
__device__ __forceinline__ void cp16(unsigned d, const void* s) {
    asm volatile("cp.async.ca.shared.global [%0], [%1], 16;" :: "r"(d), "l"(s));
}
__device__ __forceinline__ void cp_commit() {
    asm volatile("cp.async.commit_group;");
}

// ================= K1 (R9 compute; min-4-blocks bound): =====================
#define XSROW 68

__global__ void __launch_bounds__(256, 4) k1_xstate(const float* __restrict__ x,
                                                    const float* __restrict__ A) {
    __shared__ __align__(16) float xs[2][64 * XSROW];  // 34.8 KB
    __shared__ __align__(16) ull As[2][64 * 8];        // 8 KB  [c][jp]
    __shared__ ull csum_s[8][2];

    const int tid = threadIdx.x;
    const int w = tid >> 5;
    const int l = tid & 31;
    const int chunk = blockIdx.x >> 1;
    const int half = blockIdx.x & 1;
    const long T0 = (long)chunk * 64;
    const int C0 = half * 512;

    auto issue = [&](int it, int buf) {
        const float* xbase = x + T0 * CC + C0 + it * 64;
#pragma unroll
        for (int j = 0; j < 4; j++) {
            int o = tid + j * 256;
            int t = o >> 4, sub = o & 15;
            cp16(sptr(&xs[buf][t * XSROW + sub * 4]),
                 xbase + (long)t * CC + sub * 4);
        }
        {
            int c = tid >> 2, k = tid & 3;
            cp16(sptr(&As[buf][c * 8 + k * 2]),
                 A + (C0 + it * 64 + c) * SS + k * 4);
        }
        cp_commit();
    };

    issue(0, 0);
    issue(1, 1);

    ull acc[2][8];
#pragma unroll
    for (int t = 0; t < 2; t++)
#pragma unroll
        for (int jp = 0; jp < 8; jp++) acc[t][jp] = 0ull;

    for (int it = 0; it < 8; it++) {
        const int buf = it & 1;
        if (it < 7)
            asm volatile("cp.async.wait_group 1;");
        else
            asm volatile("cp.async.wait_group 0;");
        __syncthreads();

        const float* xa = &xs[buf][l * XSROW + w * 8];
        const float* xb = &xs[buf][(32 + l) * XSROW + w * 8];
        const ull* Arow = &As[buf][w * 8 * 8];

#pragma unroll
        for (int cc = 0; cc < 2; cc++) {
            float4 va = *reinterpret_cast<const float4*>(xa + cc * 4);
            float4 vb = *reinterpret_cast<const float4*>(xb + cc * 4);
            float fa[4] = {va.x, va.y, va.z, va.w};
            float fb[4] = {vb.x, vb.y, vb.z, vb.w};
#pragma unroll
            for (int k = 0; k < 4; k++) {
                const int c = cc * 4 + k;
                ull xda = dup2(fa[k]);
                ull xdb = dup2(fb[k]);
#pragma unroll
                for (int jq = 0; jq < 4; jq++) {
                    ulonglong2 a2 = *reinterpret_cast<const ulonglong2*>(
                        Arow + c * 8 + jq * 2);
                    fma2(acc[0][jq * 2], xda, a2.x);
                    fma2(acc[0][jq * 2 + 1], xda, a2.y);
                    fma2(acc[1][jq * 2], xdb, a2.x);
                    fma2(acc[1][jq * 2 + 1], xdb, a2.y);
                }
            }
        }
        __syncthreads();
        if (it + 2 < 8) issue(it + 2, buf);
    }

    // ---- cross-eighth reduce (alias xs as red[8 e][64 t][8 jp] ull) ----
    __syncthreads();
    ull* red = reinterpret_cast<ull*>(&xs[0][0]);
#pragma unroll
    for (int jp = 0; jp < 8; jp++) {
        red[((w * 64) + l) * 8 + jp] = acc[0][jp];
        red[((w * 64) + 32 + l) * 8 + jp] = acc[1][jp];
    }
    __syncthreads();

    const int jj = tid >> 6;  // 0..3 -> states 4jj..4jj+3
    const int t = tid & 63;
    ull s0 = 0ull, s1 = 0ull;
#pragma unroll
    for (int e = 0; e < 8; e++) {
        ulonglong2 v = *reinterpret_cast<const ulonglong2*>(
            &red[(e * 64 + t) * 8 + jj * 2]);
        s0 = add2(s0, v.x);
        s1 = add2(s1, v.y);
    }
    // Transposed store: [half][state][token], coalesced STG.32 per state
    {
        float f0, f1, f2, f3;
        unpack2(s0, f0, f1);
        unpack2(s1, f2, f3);
        g_xstate_t[half][4 * jj + 0][T0 + t] = f0;
        g_xstate_t[half][4 * jj + 1][T0 + t] = f1;
        g_xstate_t[half][4 * jj + 2][T0 + t] = f2;
        g_xstate_t[half][4 * jj + 3][T0 + t] = f3;
    }

    // chunk sum over 64 tokens
#pragma unroll
    for (int o = 16; o; o >>= 1) {
        s0 = add2(s0, __shfl_xor_sync(0xffffffffu, s0, o));
        s1 = add2(s1, __shfl_xor_sync(0xffffffffu, s1, o));
    }
    if (l == 0) {
        csum_s[w][0] = s0;
        csum_s[w][1] = s1;
    }
    __syncthreads();
    if (tid < 4) {
        ulonglong2 v;
        v.x = add2(csum_s[2 * tid][0], csum_s[2 * tid + 1][0]);
        v.y = add2(csum_s[2 * tid][1], csum_s[2 * tid + 1][1]);
        *reinterpret_cast<ulonglong2*>(
            &g_chsum[half][chunk * SS + tid * 4]) = v;
    }
}

// ================= K2: exclusive scan of chunk sums (unchanged) =============
__global__ void __launch_bounds__(128) k2_scan() {
    const int b = blockIdx.x >> 2;
    const int jg = blockIdx.x & 3;
    const int ch = threadIdx.x;
    const long idx = ((long)b * NCHUNK + ch) * SS + jg * 4;

    float4 s0 = *reinterpret_cast<const float4*>(&g_chsum[0][idx]);
    float4 s1 = *reinterpret_cast<const float4*>(&g_chsum[1][idx]);
    float4 s = make_float4(s0.x + s1.x, s0.y + s1.y, s0.z + s1.z, s0.w + s1.w);

    __shared__ float4 sc[NCHUNK];
    sc[ch] = s;
    __syncthreads();
    float4 v = s;
    for (int o = 1; o < NCHUNK; o <<= 1) {
        float4 u = (ch >= o) ? sc[ch - o] : make_float4(0.f, 0.f, 0.f, 0.f);
        __syncthreads();
        v.x += u.x; v.y += u.y; v.z += u.z; v.w += u.w;
        sc[ch] = v;
        __syncthreads();
    }
    float4 e = make_float4(v.x - s.x, v.y - s.y, v.z - s.z, v.w - s.w);
    *reinterpret_cast<float4*>(&g_cprefix[idx]) = e;
}

// ================= K3: cumsum + (cumstate @ D), bulk-store epilogue =========
// Grid = 1024: block = (64-token chunk) x (512-c half), 256 thr = 8 warps.
// Output staged in smem (STS.64) and drained by cp.async.bulk (2KB/token row),
// double-buffered 8-token tiles -> zero STG instructions.
__global__ void __launch_bounds__(256) k3_out(const float* __restrict__ Dg,
                                              float* __restrict__ out) {
    __shared__ __align__(16) ull cs_s[CHUNK][SS + 2];  // 8.4 KB
    __shared__ __align__(16) float stg[2][8 * 512];    // 32 KB staging

    const int tid = threadIdx.x;
    const int chunk = blockIdx.x >> 1;
    const int half = blockIdx.x & 1;
    const long T0 = (long)chunk * 64;
    const int w = tid >> 5;
    const int l = tid & 31;

    // D fragment (independent of scan): c = half*512 + 2*tid (+0,1)
    const int cbase = half * 512 + tid * 2;
    ull dfrag[SS];
#pragma unroll
    for (int j = 0; j < SS; j++)
        dfrag[j] = *reinterpret_cast<const ull*>(Dg + j * CC + cbase);

    // Warp w: cumsum for states 2w, 2w+1; coalesced reads (lane = token).
#pragma unroll
    for (int jj = 0; jj < 2; jj++) {
        const int j = w * 2 + jj;
        const float pfx = g_cprefix[chunk * SS + j];
        float v0 = g_xstate_t[0][j][T0 + l] + g_xstate_t[1][j][T0 + l];
        float v1 = g_xstate_t[0][j][T0 + 32 + l] + g_xstate_t[1][j][T0 + 32 + l];
#pragma unroll
        for (int o = 1; o < 32; o <<= 1) {
            float u = __shfl_up_sync(0xffffffffu, v0, o);
            if (l >= o) v0 += u;
        }
        const float carry = __shfl_sync(0xffffffffu, v0, 31);
#pragma unroll
        for (int o = 1; o < 32; o <<= 1) {
            float u = __shfl_up_sync(0xffffffffu, v1, o);
            if (l >= o) v1 += u;
        }
        cs_s[l][j] = dup2(v0 + pfx);
        cs_s[32 + l][j] = dup2(v1 + pfx + carry);
    }
    __syncthreads();

    float* obase = out + T0 * CC + half * 512;
    const int c2 = tid * 2;  // c within half

#pragma unroll
    for (int tile = 0; tile < 8; tile++) {
        const int buf = tile & 1;
        // Buffer reuse: ensure the bulk group that read this buffer is done.
        if (tile >= 2) {
            if (tid == 0)
                asm volatile("cp.async.bulk.wait_group.read 1;" ::: "memory");
            __syncthreads();
        }

#pragma unroll
        for (int k = 0; k < 8; k++) {
            const int tt = tile * 8 + k;
            ull oa = 0ull, ob = 0ull;
#pragma unroll
            for (int q = 0; q < 8; q++) {
                ulonglong2 cv =
                    *reinterpret_cast<const ulonglong2*>(&cs_s[tt][q * 2]);
                fma2(oa, cv.x, dfrag[2 * q]);
                fma2(ob, cv.y, dfrag[2 * q + 1]);
            }
            asm("add.rn.f32x2 %0, %0, %1;" : "+l"(oa) : "l"(ob));
            *reinterpret_cast<ull*>(&stg[buf][k * 512 + c2]) = oa;  // STS.64
        }
        __syncthreads();  // staging complete

        if (tid == 0) {
            asm volatile("fence.proxy.async.shared::cta;" ::: "memory");
#pragma unroll
            for (int k = 0; k < 8; k++) {
                asm volatile(
                    "cp.async.bulk.global.shared::cta.bulk_group [%0], [%1], 2048;"
                    :: "l"(obase + (long)(tile * 8 + k) * CC),
                       "r"(sptr(&stg[buf][k * 512]))
                    : "memory");
            }
            asm volatile("cp.async.bulk.commit_group;" ::: "memory");
        }
    }
    if (tid == 0)
        asm volatile("cp.async.bulk.wait_group 0;" ::: "memory");
}

extern "C" void kernel_launch(void* const* d_in, const int* in_sizes, int n_in,
                              void* d_out, int out_size) {
    const float* x = (const float*)d_in[0];
    const float* A = (const float*)d_in[1];
    const float* D = (const float*)d_in[2];
    float* out = (float*)d_out;

    k1_xstate<<<NCHUNKS_TOT * 2, 256>>>(x, A);
    k2_scan<<<16, 128>>>();
    k3_out<<<NCHUNKS_TOT * 2, 256>>>(D, out);
}

// round 12
// speedup vs baseline: 1.0727x; 1.0727x over previous
#include <cuda_runtime.h>
#include <cuda_bf16.h>

#define BB 4
#define NN 8192
#define CC 1024
#define SS 16
#define NTOK (BB * NN)             // 32768
#define CHUNK 64
#define NCHUNK (NN / CHUNK)        // 128 per batch
#define NCHUNKS_TOT (BB * NCHUNK)  // 512

typedef unsigned long long ull;

// Partial per-token state, TRANSPOSED: [half][state][token], 2 x 2 MB (L2)
__device__ float g_xstate_t[2][SS][NTOK];
// Partial per-chunk raw sums per c-half
__device__ float g_chsum[2][NCHUNKS_TOT * SS];
// Exclusive per-chunk prefixes (combined)
__device__ float g_cprefix[NCHUNKS_TOT * SS];

// ---------- packed f32x2 + async helpers ----------
__device__ __forceinline__ ull dup2(float x) {
    ull r;
    unsigned u = __float_as_uint(x);
    asm("mov.b64 %0, {%1, %1};" : "=l"(r) : "r"(u));
    return r;
}
__device__ __forceinline__ void fma2(ull& d, ull a, ull b) {
    asm("fma.rn.f32x2 %0, %1, %2, %0;" : "+l"(d) : "l"(a), "l"(b));
}
__device__ __forceinline__ ull add2(ull a, ull b) {
    ull r;
    asm("add.rn.f32x2 %0, %1, %2;" : "=l"(r) : "l"(a), "l"(b));
    return r;
}
__device__ __forceinline__ void unpack2(ull v, float& lo, float& hi) {
    unsigned a, b;
    asm("mov.b64 {%0, %1}, %2;" : "=r"(a), "=r"(b) : "l"(v));
    lo = __uint_as_float(a);
    hi = __uint_as_float(b);
}
__device__ __forceinline__ unsigned sptr(const void* p) {
    unsigned r;
    asm("{.reg .u64 t; cvta.to.shared.u64 t, %1; cvt.u32.u64 %0, t;}"
        : "=r"(r) : "l"(p));
    return r;
}
__device__ __forceinline__ void cp16(unsigned d, const void* s) {
    asm volatile("cp.async.ca.shared.global [%0], [%1], 16;" :: "r"(d), "l"(s));
}
__device__ __forceinline__ void cp_commit() {
    asm volatile("cp.async.commit_group;");
}

// ================= K1 (R9 exact — 80 regs, 41.5us): ========================
#define XSROW 68

__global__ void __launch_bounds__(256) k1_xstate(const float* __restrict__ x,
                                                 const float* __restrict__ A) {
    __shared__ __align__(16) float xs[2][64 * XSROW];  // 34.8 KB
    __shared__ __align__(16) ull As[2][64 * 8];        // 8 KB  [c][jp]
    __shared__ ull csum_s[8][2];

    const int tid = threadIdx.x;
    const int w = tid >> 5;
    const int l = tid & 31;
    const int chunk = blockIdx.x >> 1;
    const int half = blockIdx.x & 1;
    const long T0 = (long)chunk * 64;
    const int C0 = half * 512;

    auto issue = [&](int it, int buf) {
        const float* xbase = x + T0 * CC + C0 + it * 64;
#pragma unroll
        for (int j = 0; j < 4; j++) {
            int o = tid + j * 256;
            int t = o >> 4, sub = o & 15;
            cp16(sptr(&xs[buf][t * XSROW + sub * 4]),
                 xbase + (long)t * CC + sub * 4);
        }
        {
            int c = tid >> 2, k = tid & 3;
            cp16(sptr(&As[buf][c * 8 + k * 2]),
                 A + (C0 + it * 64 + c) * SS + k * 4);
        }
        cp_commit();
    };

    issue(0, 0);
    issue(1, 1);

    ull acc[2][8];
#pragma unroll
    for (int t = 0; t < 2; t++)
#pragma unroll
        for (int jp = 0; jp < 8; jp++) acc[t][jp] = 0ull;

    for (int it = 0; it < 8; it++) {
        const int buf = it & 1;
        if (it < 7)
            asm volatile("cp.async.wait_group 1;");
        else
            asm volatile("cp.async.wait_group 0;");
        __syncthreads();

        const float* xa = &xs[buf][l * XSROW + w * 8];
        const float* xb = &xs[buf][(32 + l) * XSROW + w * 8];
        const ull* Arow = &As[buf][w * 8 * 8];

#pragma unroll
        for (int cc = 0; cc < 2; cc++) {
            float4 va = *reinterpret_cast<const float4*>(xa + cc * 4);
            float4 vb = *reinterpret_cast<const float4*>(xb + cc * 4);
            float fa[4] = {va.x, va.y, va.z, va.w};
            float fb[4] = {vb.x, vb.y, vb.z, vb.w};
#pragma unroll
            for (int k = 0; k < 4; k++) {
                const int c = cc * 4 + k;
                ull xda = dup2(fa[k]);
                ull xdb = dup2(fb[k]);
#pragma unroll
                for (int jq = 0; jq < 4; jq++) {
                    ulonglong2 a2 = *reinterpret_cast<const ulonglong2*>(
                        Arow + c * 8 + jq * 2);
                    fma2(acc[0][jq * 2], xda, a2.x);
                    fma2(acc[0][jq * 2 + 1], xda, a2.y);
                    fma2(acc[1][jq * 2], xdb, a2.x);
                    fma2(acc[1][jq * 2 + 1], xdb, a2.y);
                }
            }
        }
        __syncthreads();
        if (it + 2 < 8) issue(it + 2, buf);
    }

    // ---- cross-eighth reduce (alias xs as red[8 e][64 t][8 jp] ull) ----
    __syncthreads();
    ull* red = reinterpret_cast<ull*>(&xs[0][0]);
#pragma unroll
    for (int jp = 0; jp < 8; jp++) {
        red[((w * 64) + l) * 8 + jp] = acc[0][jp];
        red[((w * 64) + 32 + l) * 8 + jp] = acc[1][jp];
    }
    __syncthreads();

    const int jj = tid >> 6;  // 0..3 -> states 4jj..4jj+3
    const int t = tid & 63;
    ull s0 = 0ull, s1 = 0ull;
#pragma unroll
    for (int e = 0; e < 8; e++) {
        ulonglong2 v = *reinterpret_cast<const ulonglong2*>(
            &red[(e * 64 + t) * 8 + jj * 2]);
        s0 = add2(s0, v.x);
        s1 = add2(s1, v.y);
    }
    // Transposed store: [half][state][token], coalesced STG.32 per state
    {
        float f0, f1, f2, f3;
        unpack2(s0, f0, f1);
        unpack2(s1, f2, f3);
        g_xstate_t[half][4 * jj + 0][T0 + t] = f0;
        g_xstate_t[half][4 * jj + 1][T0 + t] = f1;
        g_xstate_t[half][4 * jj + 2][T0 + t] = f2;
        g_xstate_t[half][4 * jj + 3][T0 + t] = f3;
    }

    // chunk sum over 64 tokens
#pragma unroll
    for (int o = 16; o; o >>= 1) {
        s0 = add2(s0, __shfl_xor_sync(0xffffffffu, s0, o));
        s1 = add2(s1, __shfl_xor_sync(0xffffffffu, s1, o));
    }
    if (l == 0) {
        csum_s[w][0] = s0;
        csum_s[w][1] = s1;
    }
    __syncthreads();
    if (tid < 4) {
        ulonglong2 v;
        v.x = add2(csum_s[2 * tid][0], csum_s[2 * tid + 1][0]);
        v.y = add2(csum_s[2 * tid][1], csum_s[2 * tid + 1][1]);
        *reinterpret_cast<ulonglong2*>(
            &g_chsum[half][chunk * SS + tid * 4]) = v;
    }
}

// ================= K2: exclusive scan of chunk sums (unchanged) =============
__global__ void __launch_bounds__(128) k2_scan() {
    const int b = blockIdx.x >> 2;
    const int jg = blockIdx.x & 3;
    const int ch = threadIdx.x;
    const long idx = ((long)b * NCHUNK + ch) * SS + jg * 4;

    float4 s0 = *reinterpret_cast<const float4*>(&g_chsum[0][idx]);
    float4 s1 = *reinterpret_cast<const float4*>(&g_chsum[1][idx]);
    float4 s = make_float4(s0.x + s1.x, s0.y + s1.y, s0.z + s1.z, s0.w + s1.w);

    __shared__ float4 sc[NCHUNK];
    sc[ch] = s;
    __syncthreads();
    float4 v = s;
    for (int o = 1; o < NCHUNK; o <<= 1) {
        float4 u = (ch >= o) ? sc[ch - o] : make_float4(0.f, 0.f, 0.f, 0.f);
        __syncthreads();
        v.x += u.x; v.y += u.y; v.z += u.z; v.w += u.w;
        sc[ch] = v;
        __syncthreads();
    }
    float4 e = make_float4(v.x - s.x, v.y - s.y, v.z - s.z, v.w - s.w);
    *reinterpret_cast<float4*>(&g_cprefix[idx]) = e;
}

// ================= K3: cumsum + (cumstate @ D), 8 c/thread ==================
// Grid = 512: block = one 64-token chunk x FULL 1024 c. 128 thr = 4 warps.
// Thread owns 8 channels (dfrag = 64 regs). Per token per thread:
// 8 broadcast LDS.128 + 64 fma2 + 2 STG.128  -> 76% fma issue efficiency.
__global__ void __launch_bounds__(128) k3_out(const float* __restrict__ Dg,
                                              float* __restrict__ out) {
    __shared__ __align__(16) ull cs_s[CHUNK][SS + 2];  // 9 KB

    const int tid = threadIdx.x;
    const int chunk = blockIdx.x;
    const long T0 = (long)chunk * 64;
    const int w = tid >> 5;
    const int l = tid & 31;

    // D fragment (independent of scan): c = 8*tid .. +7
    const int cbase = tid * 8;
    ulonglong2 dfrag[SS][2];
#pragma unroll
    for (int j = 0; j < SS; j++) {
        dfrag[j][0] = *reinterpret_cast<const ulonglong2*>(Dg + j * CC + cbase);
        dfrag[j][1] =
            *reinterpret_cast<const ulonglong2*>(Dg + j * CC + cbase + 4);
    }

    // Warp w: cumsum for states 4w..4w+3; coalesced reads (lane = token).
#pragma unroll
    for (int jj = 0; jj < 4; jj++) {
        const int j = w * 4 + jj;
        const float pfx = g_cprefix[chunk * SS + j];
        float v0 = g_xstate_t[0][j][T0 + l] + g_xstate_t[1][j][T0 + l];
        float v1 = g_xstate_t[0][j][T0 + 32 + l] + g_xstate_t[1][j][T0 + 32 + l];
#pragma unroll
        for (int o = 1; o < 32; o <<= 1) {
            float u = __shfl_up_sync(0xffffffffu, v0, o);
            if (l >= o) v0 += u;
        }
        const float carry = __shfl_sync(0xffffffffu, v0, 31);
#pragma unroll
        for (int o = 1; o < 32; o <<= 1) {
            float u = __shfl_up_sync(0xffffffffu, v1, o);
            if (l >= o) v1 += u;
        }
        cs_s[l][j] = dup2(v0 + pfx);
        cs_s[32 + l][j] = dup2(v1 + pfx + carry);
    }
    __syncthreads();

    float* op = out + T0 * CC + cbase;
#pragma unroll 2
    for (int tt = 0; tt < CHUNK; tt++) {
        ull a0 = 0ull, a1 = 0ull, a2 = 0ull, a3 = 0ull;
#pragma unroll
        for (int q = 0; q < 8; q++) {
            ulonglong2 cv =
                *reinterpret_cast<const ulonglong2*>(&cs_s[tt][q * 2]);  // bcast
            fma2(a0, cv.x, dfrag[2 * q][0].x);
            fma2(a1, cv.x, dfrag[2 * q][0].y);
            fma2(a2, cv.x, dfrag[2 * q][1].x);
            fma2(a3, cv.x, dfrag[2 * q][1].y);
            fma2(a0, cv.y, dfrag[2 * q + 1][0].x);
            fma2(a1, cv.y, dfrag[2 * q + 1][0].y);
            fma2(a2, cv.y, dfrag[2 * q + 1][1].x);
            fma2(a3, cv.y, dfrag[2 * q + 1][1].y);
        }
        ulonglong2 r0, r1;
        r0.x = a0; r0.y = a1;
        r1.x = a2; r1.y = a3;
        float* row = op + (long)tt * CC;
        *reinterpret_cast<ulonglong2*>(row) = r0;      // STG.128
        *reinterpret_cast<ulonglong2*>(row + 4) = r1;  // STG.128
    }
}

extern "C" void kernel_launch(void* const* d_in, const int* in_sizes, int n_in,
                              void* d_out, int out_size) {
    const float* x = (const float*)d_in[0];
    const float* A = (const float*)d_in[1];
    const float* D = (const float*)d_in[2];
    float* out = (float*)d_out;

    k1_xstate<<<NCHUNKS_TOT * 2, 256>>>(x, A);
    k2_scan<<<16, 128>>>();
    k3_out<<<NCHUNKS_TOT, 128>>>(D, out);
}

// round 13
// speedup vs baseline: 1.0760x; 1.0031x over previous
#include <cuda_runtime.h>
#include <cuda_bf16.h>

#define BB 4
#define NN 8192
#define CC 1024
#define SS 16
#define NTOK (BB * NN)             // 32768
#define CHUNK 64
#define NCHUNK (NN / CHUNK)        // 128 per batch
#define NCHUNKS_TOT (BB * NCHUNK)  // 512

typedef unsigned long long ull;

// Partial per-token state, TRANSPOSED: [half][state][token], 2 x 2 MB (L2)
__device__ float g_xstate_t[2][SS][NTOK];
// Partial per-chunk raw sums per c-half
__device__ float g_chsum[2][NCHUNKS_TOT * SS];
// Exclusive per-chunk prefixes (combined)
__device__ float g_cprefix[NCHUNKS_TOT * SS];

// ---------- packed f32x2 + async helpers ----------
__device__ __forceinline__ ull dup2(float x) {
    ull r;
    unsigned u = __float_as_uint(x);
    asm("mov.b64 %0, {%1, %1};" : "=l"(r) : "r"(u));
    return r;
}
__device__ __forceinline__ void fma2(ull& d, ull a, ull b) {
    asm("fma.rn.f32x2 %0, %1, %2, %0;" : "+l"(d) : "l"(a), "l"(b));
}
__device__ __forceinline__ ull add2(ull a, ull b) {
    ull r;
    asm("add.rn.f32x2 %0, %1, %2;" : "=l"(r) : "l"(a), "l"(b));
    return r;
}
__device__ __forceinline__ void unpack2(ull v, float& lo, float& hi) {
    unsigned a, b;
    asm("mov.b64 {%0, %1}, %2;" : "=r"(a), "=r"(b) : "l"(v));
    lo = __uint_as_float(a);
    hi = __uint_as_float(b);
}
__device__ __forceinline__ unsigned sptr(const void* p) {
    unsigned r;
    asm("{.reg .u64 t; cvta.to.shared.u64 t, %1; cvt.u32.u64 %0, t;}"
        : "=r"(r) : "l"(p));
    return r;
}
__device__ __forceinline__ void cp16(unsigned d, const void* s) {
    asm volatile("cp.async.ca.shared.global [%0], [%1], 16;" :: "r"(d), "l"(s));
}
__device__ __forceinline__ void cp_commit() {
    asm volatile("cp.async.commit_group;");
}
__device__ __forceinline__ void stcs64(void* p, ull v) {
    asm volatile("st.global.cs.b64 [%0], %1;" :: "l"(p), "l"(v) : "memory");
}

// ================= K1 (R9 exact — 80 regs, 41.1us): ========================
#define XSROW 68

__global__ void __launch_bounds__(256) k1_xstate(const float* __restrict__ x,
                                                 const float* __restrict__ A) {
    __shared__ __align__(16) float xs[2][64 * XSROW];  // 34.8 KB
    __shared__ __align__(16) ull As[2][64 * 8];        // 8 KB  [c][jp]
    __shared__ ull csum_s[8][2];

    const int tid = threadIdx.x;
    const int w = tid >> 5;
    const int l = tid & 31;
    const int chunk = blockIdx.x >> 1;
    const int half = blockIdx.x & 1;
    const long T0 = (long)chunk * 64;
    const int C0 = half * 512;

    auto issue = [&](int it, int buf) {
        const float* xbase = x + T0 * CC + C0 + it * 64;
#pragma unroll
        for (int j = 0; j < 4; j++) {
            int o = tid + j * 256;
            int t = o >> 4, sub = o & 15;
            cp16(sptr(&xs[buf][t * XSROW + sub * 4]),
                 xbase + (long)t * CC + sub * 4);
        }
        {
            int c = tid >> 2, k = tid & 3;
            cp16(sptr(&As[buf][c * 8 + k * 2]),
                 A + (C0 + it * 64 + c) * SS + k * 4);
        }
        cp_commit();
    };

    issue(0, 0);
    issue(1, 1);

    ull acc[2][8];
#pragma unroll
    for (int t = 0; t < 2; t++)
#pragma unroll
        for (int jp = 0; jp < 8; jp++) acc[t][jp] = 0ull;

    for (int it = 0; it < 8; it++) {
        const int buf = it & 1;
        if (it < 7)
            asm volatile("cp.async.wait_group 1;");
        else
            asm volatile("cp.async.wait_group 0;");
        __syncthreads();

        const float* xa = &xs[buf][l * XSROW + w * 8];
        const float* xb = &xs[buf][(32 + l) * XSROW + w * 8];
        const ull* Arow = &As[buf][w * 8 * 8];

#pragma unroll
        for (int cc = 0; cc < 2; cc++) {
            float4 va = *reinterpret_cast<const float4*>(xa + cc * 4);
            float4 vb = *reinterpret_cast<const float4*>(xb + cc * 4);
            float fa[4] = {va.x, va.y, va.z, va.w};
            float fb[4] = {vb.x, vb.y, vb.z, vb.w};
#pragma unroll
            for (int k = 0; k < 4; k++) {
                const int c = cc * 4 + k;
                ull xda = dup2(fa[k]);
                ull xdb = dup2(fb[k]);
#pragma unroll
                for (int jq = 0; jq < 4; jq++) {
                    ulonglong2 a2 = *reinterpret_cast<const ulonglong2*>(
                        Arow + c * 8 + jq * 2);
                    fma2(acc[0][jq * 2], xda, a2.x);
                    fma2(acc[0][jq * 2 + 1], xda, a2.y);
                    fma2(acc[1][jq * 2], xdb, a2.x);
                    fma2(acc[1][jq * 2 + 1], xdb, a2.y);
                }
            }
        }
        __syncthreads();
        if (it + 2 < 8) issue(it + 2, buf);
    }

    // ---- cross-eighth reduce (alias xs as red[8 e][64 t][8 jp] ull) ----
    __syncthreads();
    ull* red = reinterpret_cast<ull*>(&xs[0][0]);
#pragma unroll
    for (int jp = 0; jp < 8; jp++) {
        red[((w * 64) + l) * 8 + jp] = acc[0][jp];
        red[((w * 64) + 32 + l) * 8 + jp] = acc[1][jp];
    }
    __syncthreads();

    const int jj = tid >> 6;  // 0..3 -> states 4jj..4jj+3
    const int t = tid & 63;
    ull s0 = 0ull, s1 = 0ull;
#pragma unroll
    for (int e = 0; e < 8; e++) {
        ulonglong2 v = *reinterpret_cast<const ulonglong2*>(
            &red[(e * 64 + t) * 8 + jj * 2]);
        s0 = add2(s0, v.x);
        s1 = add2(s1, v.y);
    }
    // Transposed store: [half][state][token], coalesced STG.32 per state
    {
        float f0, f1, f2, f3;
        unpack2(s0, f0, f1);
        unpack2(s1, f2, f3);
        g_xstate_t[half][4 * jj + 0][T0 + t] = f0;
        g_xstate_t[half][4 * jj + 1][T0 + t] = f1;
        g_xstate_t[half][4 * jj + 2][T0 + t] = f2;
        g_xstate_t[half][4 * jj + 3][T0 + t] = f3;
    }

    // chunk sum over 64 tokens
#pragma unroll
    for (int o = 16; o; o >>= 1) {
        s0 = add2(s0, __shfl_xor_sync(0xffffffffu, s0, o));
        s1 = add2(s1, __shfl_xor_sync(0xffffffffu, s1, o));
    }
    if (l == 0) {
        csum_s[w][0] = s0;
        csum_s[w][1] = s1;
    }
    __syncthreads();
    if (tid < 4) {
        ulonglong2 v;
        v.x = add2(csum_s[2 * tid][0], csum_s[2 * tid + 1][0]);
        v.y = add2(csum_s[2 * tid][1], csum_s[2 * tid + 1][1]);
        *reinterpret_cast<ulonglong2*>(
            &g_chsum[half][chunk * SS + tid * 4]) = v;
    }
}

// ================= K2: exclusive scan of chunk sums (unchanged) =============
__global__ void __launch_bounds__(128) k2_scan() {
    const int b = blockIdx.x >> 2;
    const int jg = blockIdx.x & 3;
    const int ch = threadIdx.x;
    const long idx = ((long)b * NCHUNK + ch) * SS + jg * 4;

    float4 s0 = *reinterpret_cast<const float4*>(&g_chsum[0][idx]);
    float4 s1 = *reinterpret_cast<const float4*>(&g_chsum[1][idx]);
    float4 s = make_float4(s0.x + s1.x, s0.y + s1.y, s0.z + s1.z, s0.w + s1.w);

    __shared__ float4 sc[NCHUNK];
    sc[ch] = s;
    __syncthreads();
    float4 v = s;
    for (int o = 1; o < NCHUNK; o <<= 1) {
        float4 u = (ch >= o) ? sc[ch - o] : make_float4(0.f, 0.f, 0.f, 0.f);
        __syncthreads();
        v.x += u.x; v.y += u.y; v.z += u.z; v.w += u.w;
        sc[ch] = v;
        __syncthreads();
    }
    float4 e = make_float4(v.x - s.x, v.y - s.y, v.z - s.z, v.w - s.w);
    *reinterpret_cast<float4*>(&g_cprefix[idx]) = e;
}

// ================= K3: cumsum + (cumstate @ D), 2 c/thread, 64-reg ==========
// Grid = 1024: block = (64-token chunk) x (512-c half), 256 thr = 8 warps.
// launch_bounds(256,4) -> <=64 regs -> 4 CTAs/SM = 32 warps (2x R9's TLP).
// Streaming stores (st.global.cs) keep the 128MB output out of L2.
__global__ void __launch_bounds__(256, 4) k3_out(const float* __restrict__ Dg,
                                                 float* __restrict__ out) {
    __shared__ __align__(16) ull cs_s[CHUNK][SS + 2];

    const int tid = threadIdx.x;
    const int chunk = blockIdx.x >> 1;
    const int half = blockIdx.x & 1;
    const long T0 = (long)chunk * 64;
    const int w = tid >> 5;
    const int l = tid & 31;

    // D fragment (independent of scan): c = half*512 + 2*tid (+0,1)
    const int cbase = half * 512 + tid * 2;
    ull dfrag[SS];
#pragma unroll
    for (int j = 0; j < SS; j++)
        dfrag[j] = *reinterpret_cast<const ull*>(Dg + j * CC + cbase);

    // Warp w: cumsum for states 2w, 2w+1; coalesced reads (lane = token).
#pragma unroll
    for (int jj = 0; jj < 2; jj++) {
        const int j = w * 2 + jj;
        const float pfx = g_cprefix[chunk * SS + j];
        float v0 = g_xstate_t[0][j][T0 + l] + g_xstate_t[1][j][T0 + l];
        float v1 = g_xstate_t[0][j][T0 + 32 + l] + g_xstate_t[1][j][T0 + 32 + l];
#pragma unroll
        for (int o = 1; o < 32; o <<= 1) {
            float u = __shfl_up_sync(0xffffffffu, v0, o);
            if (l >= o) v0 += u;
        }
        const float carry = __shfl_sync(0xffffffffu, v0, 31);
#pragma unroll
        for (int o = 1; o < 32; o <<= 1) {
            float u = __shfl_up_sync(0xffffffffu, v1, o);
            if (l >= o) v1 += u;
        }
        cs_s[l][j] = dup2(v0 + pfx);
        cs_s[32 + l][j] = dup2(v1 + pfx + carry);
    }
    __syncthreads();

    float* op = out + T0 * CC + cbase;
#pragma unroll 4
    for (int tt = 0; tt < CHUNK; tt++) {
        ull oa = 0ull, ob = 0ull;
#pragma unroll
        for (int q = 0; q < 8; q++) {
            ulonglong2 c2 =
                *reinterpret_cast<const ulonglong2*>(&cs_s[tt][q * 2]);  // bcast
            fma2(oa, c2.x, dfrag[2 * q]);
            fma2(ob, c2.y, dfrag[2 * q + 1]);
        }
        asm("add.rn.f32x2 %0, %0, %1;" : "+l"(oa) : "l"(ob));
        stcs64(op + (long)tt * CC, oa);  // STG.64 streaming
    }
}

extern "C" void kernel_launch(void* const* d_in, const int* in_sizes, int n_in,
                              void* d_out, int out_size) {
    const float* x = (const float*)d_in[0];
    const float* A = (const float*)d_in[1];
    const float* D = (const float*)d_in[2];
    float* out = (float*)d_out;

    k1_xstate<<<NCHUNKS_TOT * 2, 256>>>(x, A);
    k2_scan<<<16, 128>>>();
    k3_out<<<NCHUNKS_TOT * 2, 256>>>(D, out);
}